// round 4
// baseline (speedup 1.0000x reference)
#include <cuda_runtime.h>
#include <cuda_bf16.h>
#include <math.h>

#define B_    2048
#define N_    4096
#define E_    256
#define H_    4
#define TI_   128
#define TJ_   64
#define THREADS 512
#define JSPLIT 4
#define JRANGE (N_/JSPLIT)         // 1024 j rows per block
#define NTILE (JRANGE/TJ_)         // 16 j-tiles per block
#define NCH   (NTILE*2)            // 32 half-chunks (2 heads each)
#define AFLOATS (TI_*E_)           // 32768
#define BFLOATS (TJ_*128)          // 8192
#define SMEM_BYTES ((AFLOATS + 2*BFLOATS)*4 + JRANGE*4)   // 200704

static __device__ float    g_F[N_ * E_];      // normalized*sqrt(C2) features [i][e]
static __device__ unsigned g_bits[B_];        // 10-bit label masks
static __device__ float    g_R[N_ * H_];      // sum_{j!=i} exp(dot/T)
static __device__ float    g_cnt[N_ * H_];    // positives count per (i, argmax head)
static __device__ float    g_dot[N_];         // sum mask * bestdot_scaled

// ---------------- helpers ----------------
__device__ __forceinline__ unsigned long long ffma2(unsigned long long a,
                                                    unsigned long long b,
                                                    unsigned long long c) {
    asm("fma.rn.f32x2 %0, %1, %2, %0;" : "+l"(c) : "l"(a), "l"(b));
    return c;
}
__device__ __forceinline__ float ex2f(float x) {
    float r; asm("ex2.approx.ftz.f32 %0, %1;" : "=f"(r) : "f"(x)); return r;
}
__device__ __forceinline__ void cpasync16(float* dst, const float* src) {
    unsigned d = (unsigned)__cvta_generic_to_shared(dst);
    asm volatile("cp.async.cg.shared.global [%0], [%1], 16;" :: "r"(d), "l"(src));
}
// monotonic (bestdot, head) packing: order-preserving uint encoding, head in low 2 bits
__device__ __forceinline__ unsigned encMax(unsigned best, float dt, unsigned h) {
    unsigned u = __float_as_uint(dt);
    unsigned m = (unsigned)(((int)u) >> 31) | 0x80000000u;
    unsigned e = ((u ^ m) & 0xFFFFFFFCu) | h;
    return best > e ? best : e;
}
__device__ __forceinline__ float decDt(unsigned enc) {
    unsigned ue = enc & 0xFFFFFFFCu;
    unsigned m = (~(unsigned)(((int)enc) >> 31)) | 0x80000000u;
    return __uint_as_float(ue ^ m);
}

// A tile: [128][256] floats, float4-slot swizzle: slot = r*64 + (c4 ^ (r&7))
__device__ __forceinline__ void loadA(float* dst, int i0, int tid) {
#pragma unroll
    for (int t = 0; t < 16; ++t) {
        int idx = t * THREADS + tid;
        int r = idx >> 6, c4 = idx & 63;
        int slot = r * 64 + (c4 ^ (r & 7));
        cpasync16(dst + slot * 4, g_F + (i0 + r) * E_ + c4 * 4);
    }
}
// B half tile: [64][128] floats, slot = r*32 + (c4 ^ (r&7))
__device__ __forceinline__ void loadB(float* dst, int j0, int half, int tid) {
#pragma unroll
    for (int t = 0; t < 4; ++t) {
        int idx = t * THREADS + tid;
        int r = idx >> 5, c4 = idx & 31;
        int slot = r * 32 + (c4 ^ (r & 7));
        cpasync16(dst + slot * 4, g_F + (j0 + r) * E_ + half * 128 + c4 * 4);
    }
}

// ---------------- preprocessing ----------------
__global__ void zeroK() {
    int t = blockIdx.x * blockDim.x + threadIdx.x;
    if (t < N_ * H_) { g_R[t] = 0.f; g_cnt[t] = 0.f; }
    if (t < N_) g_dot[t] = 0.f;
}

__global__ void bitsK(const float* __restrict__ labels) {
    int b = blockIdx.x * blockDim.x + threadIdx.x;
    if (b < B_) {
        unsigned m = 0;
#pragma unroll
        for (int k = 0; k < 10; ++k)
            if (labels[b * 10 + k] > 0.5f) m |= (1u << k);
        g_bits[b] = m;
    }
}

__global__ void normK(const float* __restrict__ feat) {
    int i = blockIdx.x;           // 0..4095   (i = v*B + b, view-major stacking)
    int e = threadIdx.x;          // 0..255
    int v = i >> 11, b = i & (B_ - 1);
    float val = feat[(b * 2 + v) * E_ + e];
    float sq = val * val;
#pragma unroll
    for (int o = 16; o; o >>= 1) sq += __shfl_xor_sync(0xffffffffu, sq, o);
    __shared__ float ws[8];
    if ((e & 31) == 0) ws[e >> 5] = sq;
    __syncthreads();
    int h = e >> 6;                          // per-head (64-dim) normalization
    float s  = ws[2 * h] + ws[2 * h + 1];
    float inv = 1.0f / fmaxf(sqrtf(s), 1e-12f);
    // fold sqrt(log2(e)/T) into the features: dots come out pre-scaled by C2
    g_F[i * E_ + e] = val * inv * 4.53981654f;   // sqrt(20.60992915555662)
}

// ---------------- main compute: one half-chunk (2 heads) ----------------
template <int HALF>
__device__ __forceinline__ void computeChunk(
    const float* __restrict__ As, const float* __restrict__ Bc,
    const unsigned* __restrict__ sBits,
    int i_base, int j0loc, int ti, int tj,
    float (&R)[4][4], unsigned (&bp)[4][4],
    float (&cdot)[4], unsigned (&cp_)[4], const unsigned (&bI)[4])
{
    const int sB = tj & 7;
    const int sA = ti & 7;
    // diag possible only when this j-tile's global rows intersect [i_base, i_base+TI_)
    const int joff = j0loc - (i_base & (JRANGE - 1));   // valid only when block hits diag
    const bool diagP = (blockIdx.y == (unsigned)(i_base / JRANGE)) &&
                       ((unsigned)joff < (unsigned)TI_);
    const float* aB = As + ti * E_;
    const float* bB = Bc + tj * 128;

#pragma unroll
    for (int h2 = 0; h2 < 2; ++h2) {
        const int hh = HALF * 2 + h2;
        unsigned long long acc[4][4];
#pragma unroll
        for (int u = 0; u < 4; ++u)
#pragma unroll
            for (int v = 0; v < 4; ++v) acc[u][v] = 0ull;
        const float* aP = aB + hh * 64;
        const float* bP = bB + h2 * 64;
#pragma unroll
        for (int k4 = 0; k4 < 16; ++k4) {
            const int xb = (k4 ^ sB) * 4;
            const int xa = (k4 ^ sA) * 4;
            ulonglong2 bv[4];
#pragma unroll
            for (int v = 0; v < 4; ++v)
                bv[v] = *(const ulonglong2*)(bP + v * 2048 + xb);
            ulonglong2 av[4];
#pragma unroll
            for (int u = 0; u < 4; ++u)
                av[u] = *(const ulonglong2*)(aP + u * 8192 + xa);
#pragma unroll
            for (int u = 0; u < 4; ++u)
#pragma unroll
                for (int v = 0; v < 4; ++v) {
                    acc[u][v] = ffma2(av[u].x, bv[v].x, acc[u][v]);
                    acc[u][v] = ffma2(av[u].y, bv[v].y, acc[u][v]);
                }
        }
#pragma unroll
        for (int u = 0; u < 4; ++u)
#pragma unroll
            for (int v = 0; v < 4; ++v) {
                float lo = __uint_as_float((unsigned)(acc[u][v] & 0xFFFFFFFFull));
                float hi = __uint_as_float((unsigned)(acc[u][v] >> 32));
                float dt = lo + hi;              // = dot(i,j,hh) * log2(e)/T
                float e  = ex2f(dt);             // = exp(dot/T)
                if (diagP && (ti + 32 * u) == (joff + tj + 16 * v)) e = 0.f;
                R[u][hh] += e;
                bp[u][v] = encMax(bp[u][v], dt, (unsigned)hh);
            }
    }

    if (HALF == 1) {   // all 4 heads seen for this tile: masked accumulation
        unsigned bJ[4];
#pragma unroll
        for (int v = 0; v < 4; ++v)
            bJ[v] = sBits[j0loc + tj + 16 * v];
#pragma unroll
        for (int u = 0; u < 4; ++u) {
#pragma unroll
            for (int v = 0; v < 4; ++v) {
                bool m = ((bI[u] & bJ[v]) != 0u);
                if (diagP && (ti + 32 * u) == (joff + tj + 16 * v)) m = false;
                if (m) {
                    unsigned e = bp[u][v];
                    cdot[u] += decDt(e);
                    cp_[u]  += 1u << ((e & 3u) * 8);
                }
                bp[u][v] = 0u;   // 0 < any real encoding
            }
        }
    }
}

__global__ void __launch_bounds__(THREADS, 1) mainK() {
    extern __shared__ float sm[];
    float* As  = sm;
    float* Bb0 = sm + AFLOATS;
    float* Bb1 = sm + AFLOATS + BFLOATS;
    unsigned* sBits = (unsigned*)(sm + AFLOATS + 2 * BFLOATS);

    const int tid = threadIdx.x;
    const int ti = tid >> 4;       // 0..31 -> i rows ti+32u, u<4
    const int tj = tid & 15;       // 0..15 -> j rows tj+16v, v<4
    const int i_base = blockIdx.x * TI_;
    const int j_base = blockIdx.y * JRANGE;

    loadA(As, i_base, tid);
    loadB(Bb0, j_base, 0, tid);
    asm volatile("cp.async.commit_group;" ::: "memory");
    loadB(Bb1, j_base, 1, tid);
    asm volatile("cp.async.commit_group;" ::: "memory");

    // stage this block's j-range label bits (j mod B_ indexing)
    for (int t = tid; t < JRANGE; t += THREADS)
        sBits[t] = g_bits[(j_base + t) & (B_ - 1)];

    float R[4][4]; unsigned bp[4][4]; float cdot[4]; unsigned cp_[4]; unsigned bI[4];
#pragma unroll
    for (int u = 0; u < 4; ++u) {
        bI[u] = g_bits[(i_base + ti + 32 * u) & (B_ - 1)];
        cdot[u] = 0.f; cp_[u] = 0u;
#pragma unroll
        for (int h = 0; h < 4; ++h) { R[u][h] = 0.f; bp[u][h] = 0u; }
    }

    for (int c = 0; c < NCH; ++c) {
        if (c == NCH - 1) asm volatile("cp.async.wait_group 0;" ::: "memory");
        else              asm volatile("cp.async.wait_group 1;" ::: "memory");
        __syncthreads();
        const int j0loc = (c >> 1) * TJ_;
        const float* Bc = (c & 1) ? Bb1 : Bb0;
        if (c & 1) computeChunk<1>(As, Bc, sBits, i_base, j0loc, ti, tj, R, bp, cdot, cp_, bI);
        else       computeChunk<0>(As, Bc, sBits, i_base, j0loc, ti, tj, R, bp, cdot, cp_, bI);
        __syncthreads();
        if (c + 2 < NCH) {
            int cn = c + 2;
            loadB((c & 1) ? Bb1 : Bb0, j_base + (cn >> 1) * TJ_, cn & 1, tid);
            asm volatile("cp.async.commit_group;" ::: "memory");
        }
    }

    // reduce across the 16 tj-lanes (offsets 8..1 stay within the half-warp group)
    float cntf[4][4];
#pragma unroll
    for (int u = 0; u < 4; ++u)
#pragma unroll
        for (int h = 0; h < 4; ++h)
            cntf[u][h] = (float)((cp_[u] >> (8 * h)) & 255u);

#pragma unroll
    for (int o = 8; o; o >>= 1) {
#pragma unroll
        for (int u = 0; u < 4; ++u) {
            cdot[u] += __shfl_xor_sync(0xffffffffu, cdot[u], o);
#pragma unroll
            for (int h = 0; h < 4; ++h) {
                R[u][h]    += __shfl_xor_sync(0xffffffffu, R[u][h], o);
                cntf[u][h] += __shfl_xor_sync(0xffffffffu, cntf[u][h], o);
            }
        }
    }
    if (tj == 0) {
#pragma unroll
        for (int u = 0; u < 4; ++u) {
            int gi = i_base + ti + 32 * u;
            atomicAdd(&g_dot[gi], cdot[u]);
#pragma unroll
            for (int h = 0; h < 4; ++h) {
                atomicAdd(&g_R[gi * 4 + h],   R[u][h]);
                atomicAdd(&g_cnt[gi * 4 + h], cntf[u][h]);
            }
        }
    }
}

// ---------------- finalize ----------------
__global__ void finalK(float* __restrict__ out) {
    __shared__ float ss[512], sc[512];
    int tid = threadIdx.x;
    float s = 0.f, c = 0.f;
    for (int i = tid; i < N_; i += 512) {
        float ct = 0.f;
        // g_dot holds sum of scaled best dots (dot*log2e/T); *ln2 -> dot/T
        float acc = g_dot[i] * 0.6931471805599453f;
#pragma unroll
        for (int h = 0; h < 4; ++h) {
            float cn = g_cnt[i * 4 + h];
            ct  += cn;
            acc -= cn * logf(g_R[i * 4 + h]);  // ln R = maxh + logS (exact cancel)
        }
        float loss = -acc / ct;                 // NaN when ct==0, as in reference
        if (isfinite(loss)) { s += loss; c += 1.f; }
    }
    ss[tid] = s; sc[tid] = c;
    __syncthreads();
    for (int o = 256; o; o >>= 1) {
        if (tid < o) { ss[tid] += ss[tid + o]; sc[tid] += sc[tid + o]; }
        __syncthreads();
    }
    if (tid == 0) out[0] = ss[0] / sc[0];
}

// ---------------- launch ----------------
extern "C" void kernel_launch(void* const* d_in, const int* in_sizes, int n_in,
                              void* d_out, int out_size) {
    const float* features = (const float*)d_in[0];
    const float* labels   = (const float*)d_in[1];
    float* out = (float*)d_out;

    cudaFuncSetAttribute(mainK, cudaFuncAttributeMaxDynamicSharedMemorySize, SMEM_BYTES);

    zeroK<<<(N_ * H_ + 255) / 256, 256>>>();
    bitsK<<<(B_ + 255) / 256, 256>>>(labels);
    normK<<<N_, 256>>>(features);
    mainK<<<dim3(N_ / TI_, JSPLIT), THREADS, SMEM_BYTES>>>();
    finalK<<<1, 512>>>(out);
}

// round 7
// speedup vs baseline: 2.5330x; 2.5330x over previous
#include <cuda_runtime.h>
#include <cuda_bf16.h>
#include <cstdint>
#include <math.h>

#define B_  2048
#define N_  4096
#define E_  256
#define H_  4
#define MT  128
#define NT  128
#define THREADS 512
#define SF  68                       // floats per smem row (64 + 4 pad): bank = 4*qt + m4, conflict-free

// smem byte layout: bits + 4 per-head tiles (A0,B0,A1,B1)
#define SM_BITS 0                    // 128 * 4 = 512
#define TILE_B  (128 * SF * 4)       // 34816
#define SM_A0   512
#define SM_B0   (SM_A0 + TILE_B)
#define SM_A1   (SM_B0 + TILE_B)
#define SM_B1   (SM_A1 + TILE_B)
#define SMEM_TOTAL (SM_B1 + TILE_B)  // 139776

static __device__ float    g_F[N_ * E_];   // per-head normalized * sqrt(log2e/T), tf32-rounded
static __device__ unsigned g_bits[B_];
static __device__ float    g_R[N_ * H_];
static __device__ float    g_cnt[N_ * H_];
static __device__ float    g_dot[N_];

// ---------------- helpers ----------------
__device__ __forceinline__ float ex2f(float x) {
    float r; asm("ex2.approx.ftz.f32 %0, %1;" : "=f"(r) : "f"(x)); return r;
}
__device__ __forceinline__ void cpasync16(uint32_t dst, const float* src) {
    asm volatile("cp.async.cg.shared.global [%0], [%1], 16;" :: "r"(dst), "l"(src));
}
#define CP_COMMIT() asm volatile("cp.async.commit_group;" ::: "memory")
#define CP_WAIT(n)  asm volatile("cp.async.wait_group %0;" :: "n"(n) : "memory")

__device__ __forceinline__ void mma_tf32(float* c, const uint32_t* a, const uint32_t* b) {
    asm volatile(
        "mma.sync.aligned.m16n8k8.row.col.f32.tf32.tf32.f32 "
        "{%0,%1,%2,%3}, {%4,%5,%6,%7}, {%8,%9}, {%0,%1,%2,%3};\n"
        : "+f"(c[0]), "+f"(c[1]), "+f"(c[2]), "+f"(c[3])
        : "r"(a[0]), "r"(a[1]), "r"(a[2]), "r"(a[3]), "r"(b[0]), "r"(b[1]));
}
// monotonic (dot, head) packing: order-preserving uint, head in low 2 bits
__device__ __forceinline__ unsigned encHD(float dt, unsigned h) {
    unsigned u = __float_as_uint(dt);
    unsigned m = (unsigned)(((int)u) >> 31) | 0x80000000u;
    return ((u ^ m) & 0xFFFFFFFCu) | h;
}
__device__ __forceinline__ float decDt(unsigned enc) {
    unsigned ue = enc & 0xFFFFFFFCu;
    unsigned m = (~(unsigned)(((int)enc) >> 31)) | 0x80000000u;
    return __uint_as_float(ue ^ m);
}

// stage one per-head [128][64] tile into a [128][SF] buffer (2048 16B chunks, 4/thread)
__device__ __forceinline__ void loadHead(uint32_t smdst, int g0, int h, int tid) {
#pragma unroll
    for (int t = 0; t < 4; ++t) {
        int idx = t * THREADS + tid;
        int r = idx >> 4, c4 = idx & 15;
        cpasync16(smdst + (uint32_t)(r * (SF * 4) + c4 * 16),
                  g_F + (g0 + r) * E_ + h * 64 + c4 * 4);
    }
}

// ---------------- preprocessing ----------------
__global__ void zeroK() {
    int t = blockIdx.x * blockDim.x + threadIdx.x;
    if (t < N_ * H_) { g_R[t] = 0.f; g_cnt[t] = 0.f; }
    if (t < N_) g_dot[t] = 0.f;
}
__global__ void bitsK(const float* __restrict__ labels) {
    int b = blockIdx.x * blockDim.x + threadIdx.x;
    if (b < B_) {
        unsigned m = 0;
#pragma unroll
        for (int k = 0; k < 10; ++k)
            if (labels[b * 10 + k] > 0.5f) m |= (1u << k);
        g_bits[b] = m;
    }
}
__global__ void normK(const float* __restrict__ feat) {
    int i = blockIdx.x;           // i = v*B + b  (view-major stacking)
    int e = threadIdx.x;          // 0..255
    int v = i >> 11, b = i & (B_ - 1);
    float val = feat[(b * 2 + v) * E_ + e];
    float sq = val * val;
#pragma unroll
    for (int o = 16; o; o >>= 1) sq += __shfl_xor_sync(0xffffffffu, sq, o);
    __shared__ float ws[8];
    if ((e & 31) == 0) ws[e >> 5] = sq;
    __syncthreads();
    int h = e >> 6;
    float s = ws[2 * h] + ws[2 * h + 1];
    float inv = 1.0f / fmaxf(sqrtf(s), 1e-12f);
    // fold sqrt(log2(e)/T): dots emerge pre-scaled by C2 = 20.6099...
    float y = val * inv * 4.53981654f;
    uint32_t t32;
    asm("cvt.rna.tf32.f32 %0, %1;" : "=r"(t32) : "f"(y));   // round-to-nearest tf32
    g_F[i * E_ + e] = __uint_as_float(t32);
}

// ---------------- main: mma.sync tf32 GEMM + fused epilogue ----------------
__global__ void __launch_bounds__(THREADS, 1) mainK() {
    extern __shared__ char smem[];
    unsigned* sBits = (unsigned*)(smem + SM_BITS);
    const uint32_t smem_base = (uint32_t)__cvta_generic_to_shared(smem);

    const int tid = threadIdx.x;
    const int w   = tid >> 5;
    const int lid = tid & 31;
    const int wi  = w >> 2;            // 0..3 : i rows 32*wi..
    const int wj  = w & 3;             // 0..3 : j cols 32*wj..
    const int qt  = lid >> 2;          // 0..7
    const int m4  = lid & 3;           // 0..3
    const int i0 = blockIdx.x * MT;
    const int j0 = blockIdx.y * NT;
    const bool diag = (blockIdx.x == blockIdx.y);

    // ---- stage heads 0 and 1 into the two buffer pairs ----
    loadHead(smem_base + SM_A0, i0, 0, tid);
    loadHead(smem_base + SM_B0, j0, 0, tid);
    CP_COMMIT();
    loadHead(smem_base + SM_A1, i0, 1, tid);
    loadHead(smem_base + SM_B1, j0, 1, tid);
    CP_COMMIT();
    if (tid < NT) sBits[tid] = g_bits[(j0 + tid) & (B_ - 1)];

    // per-thread persistent state
    unsigned bI[4];
#pragma unroll
    for (int r4 = 0; r4 < 4; ++r4) {
        int rl = 32 * wi + 16 * (r4 >> 1) + qt + 8 * (r4 & 1);
        bI[r4] = g_bits[(i0 + rl) & (B_ - 1)];
    }
    float R[4][4];
    unsigned bp[32];
#pragma unroll
    for (int r4 = 0; r4 < 4; ++r4)
#pragma unroll
        for (int h = 0; h < 4; ++h) R[r4][h] = 0.f;
#pragma unroll
    for (int p = 0; p < 32; ++p) bp[p] = 0u;

#pragma unroll
    for (int h = 0; h < 4; ++h) {
        if (h < 3) CP_WAIT(1); else CP_WAIT(0);
        __syncthreads();

        const uint32_t aOff = (h & 1) ? SM_A1 : SM_A0;
        const uint32_t bOff = (h & 1) ? SM_B1 : SM_B0;
        const uint32_t* aB = (const uint32_t*)(smem + aOff) + (32 * wi + qt) * SF + m4;
        const uint32_t* bB = (const uint32_t*)(smem + bOff) + (32 * wj + qt) * SF + m4;

        float C[2][4][4];
#pragma unroll
        for (int mt = 0; mt < 2; ++mt)
#pragma unroll
            for (int nt = 0; nt < 4; ++nt)
#pragma unroll
                for (int k = 0; k < 4; ++k) C[mt][nt][k] = 0.f;

#pragma unroll
        for (int ks = 0; ks < 8; ++ks) {
            uint32_t a[2][4], b[4][2];
#pragma unroll
            for (int mt = 0; mt < 2; ++mt) {
                const uint32_t* p = aB + mt * (16 * SF) + ks * 8;
                a[mt][0] = p[0];
                a[mt][1] = p[8 * SF];
                a[mt][2] = p[4];
                a[mt][3] = p[8 * SF + 4];
            }
#pragma unroll
            for (int nt = 0; nt < 4; ++nt) {
                const uint32_t* p = bB + nt * (8 * SF) + ks * 8;
                b[nt][0] = p[0];
                b[nt][1] = p[4];
            }
#pragma unroll
            for (int mt = 0; mt < 2; ++mt)
#pragma unroll
                for (int nt = 0; nt < 4; ++nt)
                    mma_tf32(C[mt][nt], a[mt], b[nt]);
        }

        // per-head epilogue (registers only): exp-accumulate + running argmax
#pragma unroll
        for (int mt = 0; mt < 2; ++mt)
#pragma unroll
            for (int nt = 0; nt < 4; ++nt)
#pragma unroll
                for (int k = 0; k < 4; ++k) {
                    const int half = k >> 1;
                    const int cbit = k & 1;
                    const int rl = 32 * wi + 16 * mt + qt + 8 * half;
                    const int cl = 32 * wj + 8 * nt + 2 * m4 + cbit;
                    float d = C[mt][nt][k];          // dot * log2e/T
                    float e = ex2f(d);
                    if (diag && rl == cl) e = 0.f;
                    R[mt * 2 + half][h] += e;
                    const int bpi = (mt * 2 + half) * 8 + nt * 2 + cbit;
                    unsigned en = encHD(d, (unsigned)h);
                    bp[bpi] = bp[bpi] > en ? bp[bpi] : en;
                }

        __syncthreads();                 // everyone done reading buffer (h&1)
        if (h + 2 < 4) {                 // refill freed buffers with head h+2
            loadHead(smem_base + ((h & 1) ? SM_A1 : SM_A0), i0, h + 2, tid);
            loadHead(smem_base + ((h & 1) ? SM_B1 : SM_B0), j0, h + 2, tid);
            CP_COMMIT();
        }
    }

    // ---- masked accumulation over the 32 pairs ----
    unsigned bJv[8];
#pragma unroll
    for (int nt = 0; nt < 4; ++nt)
#pragma unroll
        for (int cbit = 0; cbit < 2; ++cbit)
            bJv[nt * 2 + cbit] = sBits[32 * wj + 8 * nt + 2 * m4 + cbit];

    float cdot[4]; unsigned cp_[4];
#pragma unroll
    for (int r4 = 0; r4 < 4; ++r4) {
        cdot[r4] = 0.f; cp_[r4] = 0u;
        const int rl = 32 * wi + 16 * (r4 >> 1) + qt + 8 * (r4 & 1);
        const unsigned bIr = bI[r4];
#pragma unroll
        for (int nt = 0; nt < 4; ++nt)
#pragma unroll
            for (int cbit = 0; cbit < 2; ++cbit) {
                const int cl = 32 * wj + 8 * nt + 2 * m4 + cbit;
                bool m = ((bIr & bJv[nt * 2 + cbit]) != 0u) && !(diag && rl == cl);
                if (m) {
                    unsigned e = bp[r4 * 8 + nt * 2 + cbit];
                    cdot[r4] += decDt(e);
                    cp_[r4]  += 1u << ((e & 3u) * 8);
                }
            }
    }

    // reduce across the 4 lanes (m4 group) sharing each row
#pragma unroll
    for (int o = 1; o <= 2; o <<= 1) {
#pragma unroll
        for (int r4 = 0; r4 < 4; ++r4) {
            cdot[r4] += __shfl_xor_sync(0xffffffffu, cdot[r4], o);
            cp_[r4]  += __shfl_xor_sync(0xffffffffu, cp_[r4], o);
#pragma unroll
            for (int h = 0; h < 4; ++h)
                R[r4][h] += __shfl_xor_sync(0xffffffffu, R[r4][h], o);
        }
    }

    if (m4 == 0) {
#pragma unroll
        for (int r4 = 0; r4 < 4; ++r4) {
            const int rl = 32 * wi + 16 * (r4 >> 1) + qt + 8 * (r4 & 1);
            const int gi = i0 + rl;
            atomicAdd(&g_dot[gi], cdot[r4]);
#pragma unroll
            for (int h = 0; h < 4; ++h) {
                atomicAdd(&g_R[gi * 4 + h], R[r4][h]);
                float cn = (float)((cp_[r4] >> (8 * h)) & 255u);
                if (cn != 0.f) atomicAdd(&g_cnt[gi * 4 + h], cn);
            }
        }
    }
}

// ---------------- finalize ----------------
__global__ void finalK(float* __restrict__ out) {
    __shared__ float ss[512], sc[512];
    int tid = threadIdx.x;
    float s = 0.f, c = 0.f;
    for (int i = tid; i < N_; i += 512) {
        float ct = 0.f;
        float acc = g_dot[i] * 0.6931471805599453f;   // scaled-dot * ln2 = dot/T
#pragma unroll
        for (int h = 0; h < 4; ++h) {
            float cn = g_cnt[i * 4 + h];
            ct  += cn;
            acc -= cn * logf(g_R[i * 4 + h]);  // ln R = maxh + logS (exact cancel)
        }
        float loss = -acc / ct;                 // NaN when ct==0, as in reference
        if (isfinite(loss)) { s += loss; c += 1.f; }
    }
    ss[tid] = s; sc[tid] = c;
    __syncthreads();
    for (int o = 256; o; o >>= 1) {
        if (tid < o) { ss[tid] += ss[tid + o]; sc[tid] += sc[tid + o]; }
        __syncthreads();
    }
    if (tid == 0) out[0] = ss[0] / sc[0];
}

// ---------------- launch ----------------
extern "C" void kernel_launch(void* const* d_in, const int* in_sizes, int n_in,
                              void* d_out, int out_size) {
    const float* features = (const float*)d_in[0];
    const float* labels   = (const float*)d_in[1];
    float* out = (float*)d_out;

    cudaFuncSetAttribute(mainK, cudaFuncAttributeMaxDynamicSharedMemorySize, SMEM_TOTAL);

    zeroK<<<(N_ * H_ + 255) / 256, 256>>>();
    bitsK<<<(B_ + 255) / 256, 256>>>(labels);
    normK<<<N_, 256>>>(features);
    mainK<<<dim3(N_ / MT, N_ / NT), THREADS, SMEM_TOTAL>>>();
    finalK<<<1, 512>>>(out);
}

// round 8
// speedup vs baseline: 2.9041x; 1.1465x over previous
#include <cuda_runtime.h>
#include <cuda_bf16.h>
#include <cstdint>
#include <math.h>

#define B_  2048
#define N_  4096
#define E_  256
#define H_  4
#define MT  128
#define NT  128
#define THREADS 512
#define SF  72                       // floats per smem row: 8B lane accesses conflict-free

// smem byte layout: bits + 4 per-head tiles (A0,B0,A1,B1)
#define SM_BITS 0                    // 128 * 4 = 512
#define TILE_B  (128 * SF * 4)       // 36864
#define SM_A0   512
#define SM_B0   (SM_A0 + TILE_B)
#define SM_A1   (SM_B0 + TILE_B)
#define SM_B1   (SM_A1 + TILE_B)
#define SMEM_TOTAL (SM_B1 + TILE_B)  // 147968

#define BIAS 64.0f                   // folded into MMA accumulator init; cancels in finalK

static __device__ float    g_F[N_ * E_];   // normalized * sqrt(log2e/T), tf32-rounded, k-permuted
static __device__ unsigned g_bits[B_];
static __device__ float    g_R[N_ * H_];   // sum_{j!=i} exp(dot/T) * 2^64
static __device__ float    g_cnt[N_ * H_];
static __device__ float    g_dot[N_];      // sum mask * (dot*log2e/T + 64)

// ---------------- helpers ----------------
__device__ __forceinline__ float ex2f(float x) {
    float r; asm("ex2.approx.ftz.f32 %0, %1;" : "=f"(r) : "f"(x)); return r;
}
__device__ __forceinline__ float lg2f(float x) {
    float r; asm("lg2.approx.f32 %0, %1;" : "=f"(r) : "f"(x)); return r;
}
__device__ __forceinline__ void cpasync16(uint32_t dst, const float* src) {
    asm volatile("cp.async.cg.shared.global [%0], [%1], 16;" :: "r"(dst), "l"(src));
}
#define CP_COMMIT() asm volatile("cp.async.commit_group;" ::: "memory")
#define CP_WAIT(n)  asm volatile("cp.async.wait_group %0;" :: "n"(n) : "memory")

__device__ __forceinline__ void mma_tf32(float* c, const uint32_t* a, const uint32_t* b) {
    asm volatile(
        "mma.sync.aligned.m16n8k8.row.col.f32.tf32.tf32.f32 "
        "{%0,%1,%2,%3}, {%4,%5,%6,%7}, {%8,%9}, {%0,%1,%2,%3};\n"
        : "+f"(c[0]), "+f"(c[1]), "+f"(c[2]), "+f"(c[3])
        : "r"(a[0]), "r"(a[1]), "r"(a[2]), "r"(a[3]), "r"(b[0]), "r"(b[1]));
}

// stage one per-head [128][64] tile into a [128][SF] buffer (2048 16B chunks, 4/thread)
__device__ __forceinline__ void loadHead(uint32_t smdst, int g0, int h, int tid) {
#pragma unroll
    for (int t = 0; t < 4; ++t) {
        int idx = t * THREADS + tid;
        int r = idx >> 4, c4 = idx & 15;
        cpasync16(smdst + (uint32_t)(r * (SF * 4) + c4 * 16),
                  g_F + (g0 + r) * E_ + h * 64 + c4 * 4);
    }
}

// ---------------- fused preprocessing: zero + bits + normalize/permute ----------------
__global__ void preK(const float* __restrict__ feat, const float* __restrict__ labels) {
    int i = blockIdx.x;           // i = v*B + b  (view-major stacking)
    int e = threadIdx.x;          // 0..255
    int v = i >> 11, b = i & (B_ - 1);

    if (e < 4) { g_R[i * 4 + e] = 0.f; g_cnt[i * 4 + e] = 0.f; }
    else if (e == 4) g_dot[i] = 0.f;
    else if (e == 5 && i < B_) {
        unsigned m = 0;
#pragma unroll
        for (int k = 0; k < 10; ++k)
            if (labels[i * 10 + k] > 0.5f) m |= (1u << k);
        g_bits[i] = m;
    }

    float val = feat[(b * 2 + v) * E_ + e];
    float sq = val * val;
#pragma unroll
    for (int o = 16; o; o >>= 1) sq += __shfl_xor_sync(0xffffffffu, sq, o);
    __shared__ float ws[8];
    if ((e & 31) == 0) ws[e >> 5] = sq;
    __syncthreads();
    int h = e >> 6;
    float s = ws[2 * h] + ws[2 * h + 1];
    float inv = 1.0f / fmaxf(sqrtf(s), 1e-12f);
    float y = val * inv * 4.53981654f;          // sqrt(log2e / 0.07)
    uint32_t t32;
    asm("cvt.rna.tf32.f32 %0, %1;" : "=r"(t32) : "f"(y));
    // k-permutation within the 8-col k-group: col c -> 2*(c&3) + (c>>2)
    int eloc = e & 63, ks = eloc >> 3, c = eloc & 7;
    int newpos = ks * 8 + 2 * (c & 3) + (c >> 2);
    g_F[i * E_ + h * 64 + newpos] = __uint_as_float(t32);
}

// ---------------- per-head epilogue (registers only) ----------------
template <bool DIAG>
__device__ __forceinline__ void headEpi(
    const float (&C)[2][4][4], int h, int wi, int wj, int qt, int m4,
    float (&R)[4][4], unsigned (&bp)[32])
{
#pragma unroll
    for (int mt = 0; mt < 2; ++mt)
#pragma unroll
        for (int nt = 0; nt < 4; ++nt)
#pragma unroll
            for (int k = 0; k < 4; ++k) {
                const int half = k >> 1, cbit = k & 1;
                float d = C[mt][nt][k];              // dot*log2e/T + 64  (> 0)
                float e = ex2f(d);                   // exp(dot/T) * 2^64
                if (DIAG) {
                    const int rl = 32 * wi + 16 * mt + qt + 8 * half;
                    const int cl = 32 * wj + 8 * nt + 2 * m4 + cbit;
                    if (rl == cl) e = 0.f;
                }
                R[mt * 2 + half][h] += e;
                const int bpi = (mt * 2 + half) * 8 + nt * 2 + cbit;
                unsigned en = (__float_as_uint(d) & 0xFFFFFFFCu) | (unsigned)h;
                bp[bpi] = bp[bpi] > en ? bp[bpi] : en;   // positive floats: uint order = float order
            }
}

template <bool DIAG>
__device__ __forceinline__ void maskAcc(
    const unsigned* sBits, const unsigned (&bI)[4], const unsigned (&bp)[32],
    int wi, int wj, int qt, int m4, float (&cdot)[4], unsigned (&cp_)[4])
{
    unsigned bJv[8];
#pragma unroll
    for (int nt = 0; nt < 4; ++nt)
#pragma unroll
        for (int cbit = 0; cbit < 2; ++cbit)
            bJv[nt * 2 + cbit] = sBits[32 * wj + 8 * nt + 2 * m4 + cbit];

#pragma unroll
    for (int r4 = 0; r4 < 4; ++r4) {
        cdot[r4] = 0.f; cp_[r4] = 0u;
        const unsigned bIr = bI[r4];
        const int rl = 32 * wi + 16 * (r4 >> 1) + qt + 8 * (r4 & 1);
#pragma unroll
        for (int nt = 0; nt < 4; ++nt)
#pragma unroll
            for (int cbit = 0; cbit < 2; ++cbit) {
                bool m = ((bIr & bJv[nt * 2 + cbit]) != 0u);
                if (DIAG) {
                    const int cl = 32 * wj + 8 * nt + 2 * m4 + cbit;
                    if (rl == cl) m = false;
                }
                if (m) {
                    unsigned e = bp[r4 * 8 + nt * 2 + cbit];
                    cdot[r4] += __uint_as_float(e & 0xFFFFFFFCu);   // biased dot
                    cp_[r4]  += 1u << ((e & 3u) * 8);
                }
            }
    }
}

// ---------------- main: mma.sync tf32 GEMM + fused epilogue ----------------
__global__ void __launch_bounds__(THREADS, 1) mainK() {
    extern __shared__ char smem[];
    unsigned* sBits = (unsigned*)(smem + SM_BITS);
    const uint32_t smem_base = (uint32_t)__cvta_generic_to_shared(smem);

    const int tid = threadIdx.x;
    const int w   = tid >> 5;
    const int lid = tid & 31;
    const int wi  = w >> 2;            // 0..3 : i rows 32*wi..
    const int wj  = w & 3;             // 0..3 : j cols 32*wj..
    const int qt  = lid >> 2;          // 0..7
    const int m4  = lid & 3;           // 0..3
    const int i0 = blockIdx.x * MT;
    const int j0 = blockIdx.y * NT;
    const bool diag = (blockIdx.x == blockIdx.y);

    loadHead(smem_base + SM_A0, i0, 0, tid);
    loadHead(smem_base + SM_B0, j0, 0, tid);
    CP_COMMIT();
    loadHead(smem_base + SM_A1, i0, 1, tid);
    loadHead(smem_base + SM_B1, j0, 1, tid);
    CP_COMMIT();
    if (tid < NT) sBits[tid] = g_bits[(j0 + tid) & (B_ - 1)];

    unsigned bI[4];
#pragma unroll
    for (int r4 = 0; r4 < 4; ++r4) {
        int rl = 32 * wi + 16 * (r4 >> 1) + qt + 8 * (r4 & 1);
        bI[r4] = g_bits[(i0 + rl) & (B_ - 1)];
    }
    float R[4][4];
    unsigned bp[32];
#pragma unroll
    for (int r4 = 0; r4 < 4; ++r4)
#pragma unroll
        for (int h = 0; h < 4; ++h) R[r4][h] = 0.f;
#pragma unroll
    for (int p = 0; p < 32; ++p) bp[p] = 0u;

#pragma unroll
    for (int h = 0; h < 4; ++h) {
        if (h < 3) CP_WAIT(1); else CP_WAIT(0);
        __syncthreads();

        const uint32_t aOff = (h & 1) ? SM_A1 : SM_A0;
        const uint32_t bOff = (h & 1) ? SM_B1 : SM_B0;
        const uint32_t* aB = (const uint32_t*)(smem + aOff) + (32 * wi + qt) * SF + 2 * m4;
        const uint32_t* bB = (const uint32_t*)(smem + bOff) + (32 * wj + qt) * SF + 2 * m4;

        float C[2][4][4];
#pragma unroll
        for (int mt = 0; mt < 2; ++mt)
#pragma unroll
            for (int nt = 0; nt < 4; ++nt)
#pragma unroll
                for (int k = 0; k < 4; ++k) C[mt][nt][k] = BIAS;   // bias folded into accum

#pragma unroll
        for (int ks = 0; ks < 8; ++ks) {
            uint32_t a[2][4], b[4][2];
#pragma unroll
            for (int mt = 0; mt < 2; ++mt) {
                uint2 lo = *(const uint2*)(aB + mt * (16 * SF) + ks * 8);
                uint2 hi = *(const uint2*)(aB + mt * (16 * SF) + 8 * SF + ks * 8);
                a[mt][0] = lo.x; a[mt][1] = hi.x; a[mt][2] = lo.y; a[mt][3] = hi.y;
            }
#pragma unroll
            for (int nt = 0; nt < 4; ++nt) {
                uint2 bv = *(const uint2*)(bB + nt * (8 * SF) + ks * 8);
                b[nt][0] = bv.x; b[nt][1] = bv.y;
            }
#pragma unroll
            for (int mt = 0; mt < 2; ++mt)
#pragma unroll
                for (int nt = 0; nt < 4; ++nt)
                    mma_tf32(C[mt][nt], a[mt], b[nt]);
        }

        if (diag) headEpi<true >(C, h, wi, wj, qt, m4, R, bp);
        else      headEpi<false>(C, h, wi, wj, qt, m4, R, bp);

        __syncthreads();
        if (h + 2 < 4) {
            loadHead(smem_base + ((h & 1) ? SM_A1 : SM_A0), i0, h + 2, tid);
            loadHead(smem_base + ((h & 1) ? SM_B1 : SM_B0), j0, h + 2, tid);
            CP_COMMIT();
        }
    }

    float cdot[4]; unsigned cp_[4];
    if (diag) maskAcc<true >(sBits, bI, bp, wi, wj, qt, m4, cdot, cp_);
    else      maskAcc<false>(sBits, bI, bp, wi, wj, qt, m4, cdot, cp_);

    // reduce across the 4 lanes (m4 group) sharing each row
#pragma unroll
    for (int o = 1; o <= 2; o <<= 1) {
#pragma unroll
        for (int r4 = 0; r4 < 4; ++r4) {
            cdot[r4] += __shfl_xor_sync(0xffffffffu, cdot[r4], o);
            cp_[r4]  += __shfl_xor_sync(0xffffffffu, cp_[r4], o);
#pragma unroll
            for (int h = 0; h < 4; ++h)
                R[r4][h] += __shfl_xor_sync(0xffffffffu, R[r4][h], o);
        }
    }

    if (m4 == 0) {
#pragma unroll
        for (int r4 = 0; r4 < 4; ++r4) {
            const int rl = 32 * wi + 16 * (r4 >> 1) + qt + 8 * (r4 & 1);
            const int gi = i0 + rl;
            atomicAdd(&g_dot[gi], cdot[r4]);
#pragma unroll
            for (int h = 0; h < 4; ++h) {
                atomicAdd(&g_R[gi * 4 + h], R[r4][h]);
                float cn = (float)((cp_[r4] >> (8 * h)) & 255u);
                if (cn != 0.f) atomicAdd(&g_cnt[gi * 4 + h], cn);
            }
        }
    }
}

// ---------------- finalize ----------------
// sum_mask log_prob = ln2 * ( sum d_biased - sum_h cnt_h * lg2(R_raw_h) )  (64*ct cancels)
__global__ void finalK(float* __restrict__ out) {
    __shared__ float ss[512], sc[512];
    int tid = threadIdx.x;
    float s = 0.f, c = 0.f;
    for (int i = tid; i < N_; i += 512) {
        float ct = 0.f;
        float acc = g_dot[i];
#pragma unroll
        for (int h = 0; h < 4; ++h) {
            float cn = g_cnt[i * 4 + h];
            ct  += cn;
            acc -= cn * lg2f(g_R[i * 4 + h]);
        }
        float loss = -0.6931471805599453f * acc / ct;   // NaN when ct==0, as in reference
        if (isfinite(loss)) { s += loss; c += 1.f; }
    }
    ss[tid] = s; sc[tid] = c;
    __syncthreads();
    for (int o = 256; o; o >>= 1) {
        if (tid < o) { ss[tid] += ss[tid + o]; sc[tid] += sc[tid + o]; }
        __syncthreads();
    }
    if (tid == 0) out[0] = ss[0] / sc[0];
}

// ---------------- launch ----------------
extern "C" void kernel_launch(void* const* d_in, const int* in_sizes, int n_in,
                              void* d_out, int out_size) {
    const float* features = (const float*)d_in[0];
    const float* labels   = (const float*)d_in[1];
    float* out = (float*)d_out;

    cudaFuncSetAttribute(mainK, cudaFuncAttributeMaxDynamicSharedMemorySize, SMEM_TOTAL);

    preK<<<N_, 256>>>(features, labels);
    mainK<<<dim3(N_ / MT, N_ / NT), THREADS, SMEM_TOTAL>>>();
    finalK<<<1, 512>>>(out);
}

// round 9
// speedup vs baseline: 2.9186x; 1.0050x over previous
#include <cuda_runtime.h>
#include <cuda_bf16.h>
#include <cstdint>
#include <math.h>

#define B_  2048
#define N_  4096
#define E_  256
#define H_  4
#define MT  128
#define NT  128
#define THREADS 512
#define SF  72                       // floats per smem row: 8B lane accesses conflict-free
#define NBLK 32                      // N_/128
#define NCTA (NBLK*(NBLK+1)/2)       // 528 triangular tiles

// smem byte layout: bits + 4 per-head tiles (A0,B0,A1,B1)
#define SM_BITS 0                    // 128 * 4 = 512
#define TILE_B  (128 * SF * 4)       // 36864
#define SM_A0   512
#define SM_B0   (SM_A0 + TILE_B)
#define SM_A1   (SM_B0 + TILE_B)
#define SM_B1   (SM_A1 + TILE_B)
#define SMEM_TOTAL (SM_B1 + TILE_B)  // 147968

#define BIAS 64.0f                   // folded into MMA accumulator init; cancels in finalK

static __device__ float    g_F[N_ * E_];   // normalized * sqrt(log2e/T), tf32-rounded, k-permuted
static __device__ unsigned g_bits[B_];
static __device__ float    g_R[N_ * H_];   // sum_{j!=i} exp(dot/T) * 2^64
static __device__ float    g_cnt[N_ * H_];
static __device__ float    g_dot[N_];      // sum mask * (dot*log2e/T + 64)

// ---------------- helpers ----------------
__device__ __forceinline__ float ex2f(float x) {
    float r; asm("ex2.approx.ftz.f32 %0, %1;" : "=f"(r) : "f"(x)); return r;
}
__device__ __forceinline__ float lg2f(float x) {
    float r; asm("lg2.approx.f32 %0, %1;" : "=f"(r) : "f"(x)); return r;
}
__device__ __forceinline__ void cpasync16(uint32_t dst, const float* src) {
    asm volatile("cp.async.cg.shared.global [%0], [%1], 16;" :: "r"(dst), "l"(src));
}
#define CP_COMMIT() asm volatile("cp.async.commit_group;" ::: "memory")
#define CP_WAIT(n)  asm volatile("cp.async.wait_group %0;" :: "n"(n) : "memory")

__device__ __forceinline__ void mma_tf32(float* c, const uint32_t* a, const uint32_t* b) {
    asm volatile(
        "mma.sync.aligned.m16n8k8.row.col.f32.tf32.tf32.f32 "
        "{%0,%1,%2,%3}, {%4,%5,%6,%7}, {%8,%9}, {%0,%1,%2,%3};\n"
        : "+f"(c[0]), "+f"(c[1]), "+f"(c[2]), "+f"(c[3])
        : "r"(a[0]), "r"(a[1]), "r"(a[2]), "r"(a[3]), "r"(b[0]), "r"(b[1]));
}

// stage one per-head [128][64] tile into a [128][SF] buffer (2048 16B chunks, 4/thread)
__device__ __forceinline__ void loadHead(uint32_t smdst, int g0, int h, int tid) {
#pragma unroll
    for (int t = 0; t < 4; ++t) {
        int idx = t * THREADS + tid;
        int r = idx >> 4, c4 = idx & 15;
        cpasync16(smdst + (uint32_t)(r * (SF * 4) + c4 * 16),
                  g_F + (g0 + r) * E_ + h * 64 + c4 * 4);
    }
}

// ---------------- fused preprocessing: zero + bits + normalize/permute ----------------
__global__ void preK(const float* __restrict__ feat, const float* __restrict__ labels) {
    int i = blockIdx.x;           // i = v*B + b  (view-major stacking)
    int e = threadIdx.x;          // 0..255
    int v = i >> 11, b = i & (B_ - 1);

    if (e < 4) { g_R[i * 4 + e] = 0.f; g_cnt[i * 4 + e] = 0.f; }
    else if (e == 4) g_dot[i] = 0.f;
    else if (e == 5 && i < B_) {
        unsigned m = 0;
#pragma unroll
        for (int k = 0; k < 10; ++k)
            if (labels[i * 10 + k] > 0.5f) m |= (1u << k);
        g_bits[i] = m;
    }

    float val = feat[(b * 2 + v) * E_ + e];
    float sq = val * val;
#pragma unroll
    for (int o = 16; o; o >>= 1) sq += __shfl_xor_sync(0xffffffffu, sq, o);
    __shared__ float ws[8];
    if ((e & 31) == 0) ws[e >> 5] = sq;
    __syncthreads();
    int h = e >> 6;
    float s = ws[2 * h] + ws[2 * h + 1];
    float inv = 1.0f / fmaxf(sqrtf(s), 1e-12f);
    float y = val * inv * 4.53981654f;          // sqrt(log2e / 0.07)
    uint32_t t32;
    asm("cvt.rna.tf32.f32 %0, %1;" : "=r"(t32) : "f"(y));
    // k-permutation within the 8-col k-group: col c -> 2*(c&3) + (c>>2)
    int eloc = e & 63, ks = eloc >> 3, c = eloc & 7;
    int newpos = ks * 8 + 2 * (c & 3) + (c >> 2);
    g_F[i * E_ + h * 64 + newpos] = __uint_as_float(t32);
}

// ---------------- per-head epilogue (registers only) ----------------
// DIAG: on-diagonal tile — row-side only, self-pair masked.
// !DIAG: off-diagonal tile — row-side for i PLUS column-side scatter to anchors j.
template <bool DIAG>
__device__ __forceinline__ void headEpi(
    const float (&C)[2][4][4], int h, int j0, int wi, int wj, int qt, int m4,
    float (&R)[4][4], unsigned (&bp)[32])
{
    float RjA[8];
    if (!DIAG) {
#pragma unroll
        for (int c = 0; c < 8; ++c) RjA[c] = 0.f;
    }
#pragma unroll
    for (int mt = 0; mt < 2; ++mt)
#pragma unroll
        for (int nt = 0; nt < 4; ++nt)
#pragma unroll
            for (int k = 0; k < 4; ++k) {
                const int half = k >> 1, cbit = k & 1;
                float d = C[mt][nt][k];              // dot*log2e/T + 64  (> 0)
                float e = ex2f(d);                   // exp(dot/T) * 2^64
                if (DIAG) {
                    const int rl = 32 * wi + 16 * mt + qt + 8 * half;
                    const int cl = 32 * wj + 8 * nt + 2 * m4 + cbit;
                    if (rl == cl) e = 0.f;
                }
                R[mt * 2 + half][h] += e;
                if (!DIAG) RjA[nt * 2 + cbit] += e;
                const int bpi = (mt * 2 + half) * 8 + nt * 2 + cbit;
                unsigned en = (__float_as_uint(d) & 0xFFFFFFFCu) | (unsigned)h;
                bp[bpi] = bp[bpi] > en ? bp[bpi] : en;   // positive floats: uint order = float order
            }
    if (!DIAG) {
        // reduce over qt lanes (xor 4,8,16 changes qt, keeps m4), then scatter to g_R[j,h]
#pragma unroll
        for (int o = 4; o <= 16; o <<= 1)
#pragma unroll
            for (int c = 0; c < 8; ++c)
                RjA[c] += __shfl_xor_sync(0xffffffffu, RjA[c], o);
        if (qt == 0) {
#pragma unroll
            for (int nt = 0; nt < 4; ++nt)
#pragma unroll
                for (int cbit = 0; cbit < 2; ++cbit) {
                    int gj = j0 + 32 * wj + 8 * nt + 2 * m4 + cbit;
                    atomicAdd(&g_R[gj * 4 + h], RjA[nt * 2 + cbit]);
                }
        }
    }
}

// ---------------- main: mma.sync tf32 GEMM + fused two-sided epilogue ----------------
__global__ void __launch_bounds__(THREADS, 1) mainK() {
    extern __shared__ char smem[];
    unsigned* sBits = (unsigned*)(smem + SM_BITS);
    const uint32_t smem_base = (uint32_t)__cvta_generic_to_shared(smem);

    const int tid = threadIdx.x;
    const int w   = tid >> 5;
    const int lid = tid & 31;
    const int wi  = w >> 2;            // 0..3 : i rows 32*wi..
    const int wj  = w & 3;             // 0..3 : j cols 32*wj..
    const int qt  = lid >> 2;          // 0..7
    const int m4  = lid & 3;           // 0..3

    // triangular tile decode: bx <= by
    int idx = blockIdx.x;
    int by = (int)((sqrtf(8.f * (float)idx + 1.f) - 1.f) * 0.5f);
    while ((by + 1) * (by + 2) / 2 <= idx) ++by;
    while (by * (by + 1) / 2 > idx) --by;
    int bx = idx - by * (by + 1) / 2;
    const int i0 = bx * MT;
    const int j0 = by * NT;
    const bool diag = (bx == by);

    loadHead(smem_base + SM_A0, i0, 0, tid);
    loadHead(smem_base + SM_B0, j0, 0, tid);
    CP_COMMIT();
    loadHead(smem_base + SM_A1, i0, 1, tid);
    loadHead(smem_base + SM_B1, j0, 1, tid);
    CP_COMMIT();
    if (tid < NT) sBits[tid] = g_bits[(j0 + tid) & (B_ - 1)];

    unsigned bI[4];
#pragma unroll
    for (int r4 = 0; r4 < 4; ++r4) {
        int rl = 32 * wi + 16 * (r4 >> 1) + qt + 8 * (r4 & 1);
        bI[r4] = g_bits[(i0 + rl) & (B_ - 1)];
    }
    float R[4][4];
    unsigned bp[32];
#pragma unroll
    for (int r4 = 0; r4 < 4; ++r4)
#pragma unroll
        for (int h = 0; h < 4; ++h) R[r4][h] = 0.f;
#pragma unroll
    for (int p = 0; p < 32; ++p) bp[p] = 0u;

#pragma unroll
    for (int h = 0; h < 4; ++h) {
        if (h < 3) CP_WAIT(1); else CP_WAIT(0);
        __syncthreads();

        const uint32_t aOff = (h & 1) ? SM_A1 : SM_A0;
        const uint32_t bOff = (h & 1) ? SM_B1 : SM_B0;
        const uint32_t* aB = (const uint32_t*)(smem + aOff) + (32 * wi + qt) * SF + 2 * m4;
        const uint32_t* bB = (const uint32_t*)(smem + bOff) + (32 * wj + qt) * SF + 2 * m4;

        float C[2][4][4];
#pragma unroll
        for (int mt = 0; mt < 2; ++mt)
#pragma unroll
            for (int nt = 0; nt < 4; ++nt)
#pragma unroll
                for (int k = 0; k < 4; ++k) C[mt][nt][k] = BIAS;   // bias folded into accum

#pragma unroll
        for (int ks = 0; ks < 8; ++ks) {
            uint32_t a[2][4], b[4][2];
#pragma unroll
            for (int mt = 0; mt < 2; ++mt) {
                uint2 lo = *(const uint2*)(aB + mt * (16 * SF) + ks * 8);
                uint2 hi = *(const uint2*)(aB + mt * (16 * SF) + 8 * SF + ks * 8);
                a[mt][0] = lo.x; a[mt][1] = hi.x; a[mt][2] = lo.y; a[mt][3] = hi.y;
            }
#pragma unroll
            for (int nt = 0; nt < 4; ++nt) {
                uint2 bv = *(const uint2*)(bB + nt * (8 * SF) + ks * 8);
                b[nt][0] = bv.x; b[nt][1] = bv.y;
            }
#pragma unroll
            for (int mt = 0; mt < 2; ++mt)
#pragma unroll
                for (int nt = 0; nt < 4; ++nt)
                    mma_tf32(C[mt][nt], a[mt], b[nt]);
        }

        if (diag) headEpi<true >(C, h, j0, wi, wj, qt, m4, R, bp);
        else      headEpi<false>(C, h, j0, wi, wj, qt, m4, R, bp);

        __syncthreads();
        if (h + 2 < 4) {
            loadHead(smem_base + ((h & 1) ? SM_A1 : SM_A0), i0, h + 2, tid);
            loadHead(smem_base + ((h & 1) ? SM_B1 : SM_B0), j0, h + 2, tid);
            CP_COMMIT();
        }
    }

    // ---- masked accumulation over the 32 pairs (row side; plus column side if off-diag) ----
    unsigned bJv[8];
#pragma unroll
    for (int nt = 0; nt < 4; ++nt)
#pragma unroll
        for (int cbit = 0; cbit < 2; ++cbit)
            bJv[nt * 2 + cbit] = sBits[32 * wj + 8 * nt + 2 * m4 + cbit];

    float cdot[4]; unsigned cp_[4];
    float cdotj[8]; unsigned cpj[8];
#pragma unroll
    for (int c = 0; c < 8; ++c) { cdotj[c] = 0.f; cpj[c] = 0u; }

#pragma unroll
    for (int r4 = 0; r4 < 4; ++r4) {
        cdot[r4] = 0.f; cp_[r4] = 0u;
        const unsigned bIr = bI[r4];
        const int rl = 32 * wi + 16 * (r4 >> 1) + qt + 8 * (r4 & 1);
#pragma unroll
        for (int nt = 0; nt < 4; ++nt)
#pragma unroll
            for (int cbit = 0; cbit < 2; ++cbit) {
                bool m = ((bIr & bJv[nt * 2 + cbit]) != 0u);
                if (diag) {
                    const int cl = 32 * wj + 8 * nt + 2 * m4 + cbit;
                    if (rl == cl) m = false;
                }
                if (m) {
                    unsigned e = bp[r4 * 8 + nt * 2 + cbit];
                    float dt = __uint_as_float(e & 0xFFFFFFFCu);   // biased dot
                    unsigned inc = 1u << ((e & 3u) * 8);
                    cdot[r4] += dt;
                    cp_[r4]  += inc;
                    if (!diag) { cdotj[nt * 2 + cbit] += dt; cpj[nt * 2 + cbit] += inc; }
                }
            }
    }

    // row side: reduce across the 4 m4 lanes sharing each row
#pragma unroll
    for (int o = 1; o <= 2; o <<= 1) {
#pragma unroll
        for (int r4 = 0; r4 < 4; ++r4) {
            cdot[r4] += __shfl_xor_sync(0xffffffffu, cdot[r4], o);
            cp_[r4]  += __shfl_xor_sync(0xffffffffu, cp_[r4], o);
#pragma unroll
            for (int h = 0; h < 4; ++h)
                R[r4][h] += __shfl_xor_sync(0xffffffffu, R[r4][h], o);
        }
    }
    if (m4 == 0) {
#pragma unroll
        for (int r4 = 0; r4 < 4; ++r4) {
            const int rl = 32 * wi + 16 * (r4 >> 1) + qt + 8 * (r4 & 1);
            const int gi = i0 + rl;
            atomicAdd(&g_dot[gi], cdot[r4]);
#pragma unroll
            for (int h = 0; h < 4; ++h) {
                atomicAdd(&g_R[gi * 4 + h], R[r4][h]);
                float cn = (float)((cp_[r4] >> (8 * h)) & 255u);
                if (cn != 0.f) atomicAdd(&g_cnt[gi * 4 + h], cn);
            }
        }
    }

    // column side (off-diag only): reduce across qt lanes, scatter to anchors j
    if (!diag) {
#pragma unroll
        for (int o = 4; o <= 16; o <<= 1)
#pragma unroll
            for (int c = 0; c < 8; ++c) {
                cdotj[c] += __shfl_xor_sync(0xffffffffu, cdotj[c], o);
                cpj[c]   += __shfl_xor_sync(0xffffffffu, cpj[c], o);
            }
        if (qt == 0) {
#pragma unroll
            for (int nt = 0; nt < 4; ++nt)
#pragma unroll
                for (int cbit = 0; cbit < 2; ++cbit) {
                    const int c = nt * 2 + cbit;
                    const int gj = j0 + 32 * wj + 8 * nt + 2 * m4 + cbit;
                    if (cpj[c] != 0u) {
                        atomicAdd(&g_dot[gj], cdotj[c]);
#pragma unroll
                        for (int h = 0; h < 4; ++h) {
                            float cn = (float)((cpj[c] >> (8 * h)) & 255u);
                            if (cn != 0.f) atomicAdd(&g_cnt[gj * 4 + h], cn);
                        }
                    }
                }
        }
    }
}

// ---------------- finalize ----------------
// sum_mask log_prob = ln2 * ( sum d_biased - sum_h cnt_h * lg2(R_raw_h) )  (64*ct cancels)
__global__ void finalK(float* __restrict__ out) {
    __shared__ float ss[512], sc[512];
    int tid = threadIdx.x;
    float s = 0.f, c = 0.f;
    for (int i = tid; i < N_; i += 512) {
        float ct = 0.f;
        float acc = g_dot[i];
#pragma unroll
        for (int h = 0; h < 4; ++h) {
            float cn = g_cnt[i * 4 + h];
            ct  += cn;
            acc -= cn * lg2f(g_R[i * 4 + h]);
        }
        float loss = -0.6931471805599453f * acc / ct;   // NaN when ct==0, as in reference
        if (isfinite(loss)) { s += loss; c += 1.f; }
    }
    ss[tid] = s; sc[tid] = c;
    __syncthreads();
    for (int o = 256; o; o >>= 1) {
        if (tid < o) { ss[tid] += ss[tid + o]; sc[tid] += sc[tid + o]; }
        __syncthreads();
    }
    if (tid == 0) out[0] = ss[0] / sc[0];
}

// ---------------- launch ----------------
extern "C" void kernel_launch(void* const* d_in, const int* in_sizes, int n_in,
                              void* d_out, int out_size) {
    const float* features = (const float*)d_in[0];
    const float* labels   = (const float*)d_in[1];
    float* out = (float*)d_out;

    cudaFuncSetAttribute(mainK, cudaFuncAttributeMaxDynamicSharedMemorySize, SMEM_TOTAL);

    preK<<<N_, 256>>>(features, labels);
    mainK<<<NCTA, THREADS, SMEM_TOTAL>>>();
    finalK<<<1, 512>>>(out);
}

// round 10
// speedup vs baseline: 2.9254x; 1.0023x over previous
#include <cuda_runtime.h>
#include <cuda_bf16.h>
#include <cstdint>
#include <math.h>

#define B_  2048
#define N_  4096
#define E_  256
#define H_  4
#define TILE 64
#define THREADS 256
#define SF  72                       // floats per smem row: 8B lane accesses conflict-free per phase
#define NBLK 64                      // N_/64
#define NCTA (NBLK*(NBLK+1)/2)       // 2080 triangular tiles

// smem float-index layout for accumulators (base SM_ACC)
#define SRI  0                       // [64][4] row R
#define SCDI 256                     // [64]    row dot
#define SCNI 320                     // [64][4] row cnt
#define SRJ  576                     // [64][4] col R
#define SCDJ 832                     // [64]    col dot
#define SCNJ 896                     // [64][4] col cnt
#define ACC_FLOATS 1152

// smem byte layout
#define SM_BITS 0                    // 64*4 = 256
#define SM_ACC  256                  // 4608 bytes
#define SM_A0   5120
#define TILE_B  (64 * SF * 4)        // 18432
#define SM_B0   (SM_A0 + TILE_B)
#define SM_A1   (SM_B0 + TILE_B)
#define SM_B1   (SM_A1 + TILE_B)
#define SMEM_TOTAL (SM_B1 + TILE_B)  // 78848

#define BIAS 64.0f                   // folded into MMA accumulator; cancels in finalK

static __device__ float    g_F[N_ * E_];   // normalized * sqrt(log2e/T), tf32-rounded, k-permuted
static __device__ unsigned g_bits[B_];
static __device__ float    g_R[N_ * H_];   // sum_{j!=i} exp(dot/T) * 2^64
static __device__ float    g_cnt[N_ * H_];
static __device__ float    g_dot[N_];      // sum mask * (dot*log2e/T + 64)

// ---------------- helpers ----------------
__device__ __forceinline__ float ex2f(float x) {
    float r; asm("ex2.approx.ftz.f32 %0, %1;" : "=f"(r) : "f"(x)); return r;
}
__device__ __forceinline__ float lg2f(float x) {
    float r; asm("lg2.approx.f32 %0, %1;" : "=f"(r) : "f"(x)); return r;
}
__device__ __forceinline__ void cpasync16(uint32_t dst, const float* src) {
    asm volatile("cp.async.cg.shared.global [%0], [%1], 16;" :: "r"(dst), "l"(src));
}
#define CP_COMMIT() asm volatile("cp.async.commit_group;" ::: "memory")
#define CP_WAIT(n)  asm volatile("cp.async.wait_group %0;" :: "n"(n) : "memory")

__device__ __forceinline__ void mma_tf32(float* c, const uint32_t* a, const uint32_t* b) {
    asm volatile(
        "mma.sync.aligned.m16n8k8.row.col.f32.tf32.tf32.f32 "
        "{%0,%1,%2,%3}, {%4,%5,%6,%7}, {%8,%9}, {%0,%1,%2,%3};\n"
        : "+f"(c[0]), "+f"(c[1]), "+f"(c[2]), "+f"(c[3])
        : "r"(a[0]), "r"(a[1]), "r"(a[2]), "r"(a[3]), "r"(b[0]), "r"(b[1]));
}

// stage one per-head [64][64] tile into a [64][SF] buffer (1024 16B chunks, 4/thread)
__device__ __forceinline__ void loadHead(uint32_t smdst, int g0, int h, int tid) {
#pragma unroll
    for (int t = 0; t < 4; ++t) {
        int idx = t * THREADS + tid;
        int r = idx >> 4, c4 = idx & 15;
        cpasync16(smdst + (uint32_t)(r * (SF * 4) + c4 * 16),
                  g_F + (g0 + r) * E_ + h * 64 + c4 * 4);
    }
}

// ---------------- fused preprocessing: zero + bits + normalize/permute (float4) ----------------
__global__ void preK(const float* __restrict__ feat, const float* __restrict__ labels) {
    int tid = threadIdx.x;
    int i = blockIdx.x * 4 + (tid >> 6);   // 4 rows per block; i = v*B + b
    int c4 = tid & 63;                     // 16B chunk within row
    int v = i >> 11, b = i & (B_ - 1);

    if (c4 < 4) { g_R[i * 4 + c4] = 0.f; g_cnt[i * 4 + c4] = 0.f; }
    else if (c4 == 4) g_dot[i] = 0.f;
    else if (c4 == 5 && i < B_) {
        unsigned m = 0;
#pragma unroll
        for (int k = 0; k < 10; ++k)
            if (labels[i * 10 + k] > 0.5f) m |= (1u << k);
        g_bits[i] = m;
    }

    float4 val = *(const float4*)(feat + (b * 2 + v) * E_ + c4 * 4);
    float sq = val.x * val.x + val.y * val.y + val.z * val.z + val.w * val.w;
#pragma unroll
    for (int o = 1; o <= 8; o <<= 1) sq += __shfl_xor_sync(0xffffffffu, sq, o);  // 16-lane = 1 head
    float inv = 1.0f / fmaxf(sqrtf(sq), 1e-12f);
    const float SC = 4.53981654f;          // sqrt(log2e / 0.07)
    int h = c4 >> 4;
    float* dst = g_F + i * E_ + h * 64;
    float e4[4] = {val.x, val.y, val.z, val.w};
#pragma unroll
    for (int t = 0; t < 4; ++t) {
        int eloc = (c4 & 15) * 4 + t;
        int ks = eloc >> 3, c = eloc & 7;
        int newpos = ks * 8 + 2 * (c & 3) + (c >> 2);   // k-permutation for LDS.64 frags
        float y = e4[t] * inv * SC;
        uint32_t t32;
        asm("cvt.rna.tf32.f32 %0, %1;" : "=r"(t32) : "f"(y));
        dst[newpos] = __uint_as_float(t32);
    }
}

// ---------------- main: mma.sync tf32, triangular grid, two-sided smem epilogue ----------------
__global__ void __launch_bounds__(THREADS, 2) mainK() {
    extern __shared__ char smem[];
    unsigned* sBits = (unsigned*)(smem + SM_BITS);
    float* sAcc = (float*)(smem + SM_ACC);
    const uint32_t smem_base = (uint32_t)__cvta_generic_to_shared(smem);

    const int tid = threadIdx.x;
    const int w   = tid >> 5;
    const int lid = tid & 31;
    const int wi  = w >> 2;            // 0..1 : rows 32*wi..
    const int wj  = w & 3;             // 0..3 : cols 16*wj..
    const int qt  = lid >> 2;          // 0..7
    const int m4  = lid & 3;           // 0..3

    // triangular decode: bx <= by
    int idx = blockIdx.x;
    int by = (int)((sqrtf(8.f * (float)idx + 1.f) - 1.f) * 0.5f);
    while ((by + 1) * (by + 2) / 2 <= idx) ++by;
    while (by * (by + 1) / 2 > idx) --by;
    int bx = idx - by * (by + 1) / 2;
    const int i0 = bx * TILE;
    const int j0 = by * TILE;
    const bool diag = (bx == by);

    loadHead(smem_base + SM_A0, i0, 0, tid);
    loadHead(smem_base + SM_B0, j0, 0, tid);
    CP_COMMIT();
    loadHead(smem_base + SM_A1, i0, 1, tid);
    loadHead(smem_base + SM_B1, j0, 1, tid);
    CP_COMMIT();

    if (tid < TILE) sBits[tid] = g_bits[(j0 + tid) & (B_ - 1)];
    for (int t = tid; t < ACC_FLOATS; t += THREADS) sAcc[t] = 0.f;

    unsigned bI[4];
#pragma unroll
    for (int r4 = 0; r4 < 4; ++r4) {
        int rl = 32 * wi + 16 * (r4 >> 1) + qt + 8 * (r4 & 1);
        bI[r4] = g_bits[(i0 + rl) & (B_ - 1)];
    }
    float R[4][4];
    unsigned bp[16];
#pragma unroll
    for (int r4 = 0; r4 < 4; ++r4)
#pragma unroll
        for (int h = 0; h < 4; ++h) R[r4][h] = 0.f;
#pragma unroll
    for (int p = 0; p < 16; ++p) bp[p] = 0u;

#pragma unroll
    for (int h = 0; h < 4; ++h) {
        if (h < 3) CP_WAIT(1); else CP_WAIT(0);
        __syncthreads();

        const uint32_t aOff = (h & 1) ? SM_A1 : SM_A0;
        const uint32_t bOff = (h & 1) ? SM_B1 : SM_B0;
        const uint32_t* aB = (const uint32_t*)(smem + aOff) + (32 * wi + qt) * SF + 2 * m4;
        const uint32_t* bB = (const uint32_t*)(smem + bOff) + (16 * wj + qt) * SF + 2 * m4;

        float C[2][2][4];
#pragma unroll
        for (int mt = 0; mt < 2; ++mt)
#pragma unroll
            for (int nt = 0; nt < 2; ++nt)
#pragma unroll
                for (int k = 0; k < 4; ++k) C[mt][nt][k] = BIAS;

#pragma unroll
        for (int ks = 0; ks < 8; ++ks) {
            uint32_t a[2][4], b[2][2];
#pragma unroll
            for (int mt = 0; mt < 2; ++mt) {
                uint2 lo = *(const uint2*)(aB + mt * (16 * SF) + ks * 8);
                uint2 hi = *(const uint2*)(aB + mt * (16 * SF) + 8 * SF + ks * 8);
                a[mt][0] = lo.x; a[mt][1] = hi.x; a[mt][2] = lo.y; a[mt][3] = hi.y;
            }
#pragma unroll
            for (int nt = 0; nt < 2; ++nt) {
                uint2 bv = *(const uint2*)(bB + nt * (8 * SF) + ks * 8);
                b[nt][0] = bv.x; b[nt][1] = bv.y;
            }
#pragma unroll
            for (int mt = 0; mt < 2; ++mt)
#pragma unroll
                for (int nt = 0; nt < 2; ++nt)
                    mma_tf32(C[mt][nt], a[mt], b[nt]);
        }

        // per-head epilogue
        float RjA[4] = {0.f, 0.f, 0.f, 0.f};
#pragma unroll
        for (int mt = 0; mt < 2; ++mt)
#pragma unroll
            for (int nt = 0; nt < 2; ++nt)
#pragma unroll
                for (int k = 0; k < 4; ++k) {
                    const int half = k >> 1, cbit = k & 1;
                    float d = C[mt][nt][k];          // dot*log2e/T + 64  (> 0)
                    float e = ex2f(d);               // exp(dot/T) * 2^64
                    if (diag) {
                        const int rl = 32 * wi + 16 * mt + qt + 8 * half;
                        const int cl = 16 * wj + 8 * nt + 2 * m4 + cbit;
                        if (rl == cl) e = 0.f;
                    }
                    R[mt * 2 + half][h] += e;
                    RjA[nt * 2 + cbit] += e;
                    const int bpi = (mt * 2 + half) * 4 + nt * 2 + cbit;
                    unsigned en = (__float_as_uint(d) & 0xFFFFFFFCu) | (unsigned)h;
                    bp[bpi] = bp[bpi] > en ? bp[bpi] : en;
                }
        if (!diag) {
            // column-side R: reduce over qt lanes, smem-atomic from qt==0 lanes
#pragma unroll
            for (int o = 4; o <= 16; o <<= 1)
#pragma unroll
                for (int c = 0; c < 4; ++c)
                    RjA[c] += __shfl_xor_sync(0xffffffffu, RjA[c], o);
            if (qt == 0) {
#pragma unroll
                for (int c = 0; c < 4; ++c) {
                    int cl = 16 * wj + 8 * (c >> 1) + 2 * m4 + (c & 1);
                    atomicAdd(&sAcc[SRJ + cl * 4 + h], RjA[c]);
                }
            }
        }

        __syncthreads();
        if (h + 2 < 4) {
            loadHead(smem_base + ((h & 1) ? SM_A1 : SM_A0), i0, h + 2, tid);
            loadHead(smem_base + ((h & 1) ? SM_B1 : SM_B0), j0, h + 2, tid);
            CP_COMMIT();
        }
    }

    // ---- masked accumulation (row side; plus column side if off-diag) ----
    unsigned bJv[4];
#pragma unroll
    for (int c = 0; c < 4; ++c)
        bJv[c] = sBits[16 * wj + 8 * (c >> 1) + 2 * m4 + (c & 1)];

    float cdot[4]; unsigned cp_[4];
    float cdotj[4] = {0.f, 0.f, 0.f, 0.f};
    unsigned cpj[4] = {0u, 0u, 0u, 0u};

#pragma unroll
    for (int r4 = 0; r4 < 4; ++r4) {
        cdot[r4] = 0.f; cp_[r4] = 0u;
        const unsigned bIr = bI[r4];
        const int rl = 32 * wi + 16 * (r4 >> 1) + qt + 8 * (r4 & 1);
#pragma unroll
        for (int c = 0; c < 4; ++c) {
            bool m = ((bIr & bJv[c]) != 0u);
            if (diag) {
                const int cl = 16 * wj + 8 * (c >> 1) + 2 * m4 + (c & 1);
                if (rl == cl) m = false;
            }
            if (m) {
                unsigned e = bp[r4 * 4 + c];
                float dt = __uint_as_float(e & 0xFFFFFFFCu);   // biased dot
                unsigned inc = 1u << ((e & 3u) * 8);
                cdot[r4] += dt; cp_[r4] += inc;
                cdotj[c] += dt; cpj[c]  += inc;
            }
        }
    }

    // row side: reduce over the 4 m4 lanes, smem-atomic from m4==0
#pragma unroll
    for (int o = 1; o <= 2; o <<= 1) {
#pragma unroll
        for (int r4 = 0; r4 < 4; ++r4) {
            cdot[r4] += __shfl_xor_sync(0xffffffffu, cdot[r4], o);
            cp_[r4]  += __shfl_xor_sync(0xffffffffu, cp_[r4], o);
#pragma unroll
            for (int h = 0; h < 4; ++h)
                R[r4][h] += __shfl_xor_sync(0xffffffffu, R[r4][h], o);
        }
    }
    if (m4 == 0) {
#pragma unroll
        for (int r4 = 0; r4 < 4; ++r4) {
            const int rl = 32 * wi + 16 * (r4 >> 1) + qt + 8 * (r4 & 1);
            atomicAdd(&sAcc[SCDI + rl], cdot[r4]);
#pragma unroll
            for (int h = 0; h < 4; ++h) {
                atomicAdd(&sAcc[SRI + rl * 4 + h], R[r4][h]);
                float cn = (float)((cp_[r4] >> (8 * h)) & 255u);
                if (cn != 0.f) atomicAdd(&sAcc[SCNI + rl * 4 + h], cn);
            }
        }
    }

    // column side mask results (off-diag): reduce over qt lanes, smem-atomic from qt==0
    if (!diag) {
#pragma unroll
        for (int o = 4; o <= 16; o <<= 1)
#pragma unroll
            for (int c = 0; c < 4; ++c) {
                cdotj[c] += __shfl_xor_sync(0xffffffffu, cdotj[c], o);
                cpj[c]   += __shfl_xor_sync(0xffffffffu, cpj[c], o);
            }
        if (qt == 0) {
#pragma unroll
            for (int c = 0; c < 4; ++c) {
                int cl = 16 * wj + 8 * (c >> 1) + 2 * m4 + (c & 1);
                if (cpj[c] != 0u) {
                    atomicAdd(&sAcc[SCDJ + cl], cdotj[c]);
#pragma unroll
                    for (int h = 0; h < 4; ++h) {
                        float cn = (float)((cpj[c] >> (8 * h)) & 255u);
                        if (cn != 0.f) atomicAdd(&sAcc[SCNJ + cl * 4 + h], cn);
                    }
                }
            }
        }
    }

    // ---- single coalesced global flush ----
    __syncthreads();
    if (tid < TILE) {
        const int rl = tid, gi = i0 + rl;
        atomicAdd(&g_dot[gi], sAcc[SCDI + rl]);
#pragma unroll
        for (int h = 0; h < 4; ++h) {
            atomicAdd(&g_R[gi * 4 + h], sAcc[SRI + rl * 4 + h]);
            float cn = sAcc[SCNI + rl * 4 + h];
            if (cn != 0.f) atomicAdd(&g_cnt[gi * 4 + h], cn);
        }
    } else if (!diag && tid < 2 * TILE) {
        const int cl = tid - TILE, gj = j0 + cl;
        atomicAdd(&g_dot[gj], sAcc[SCDJ + cl]);
#pragma unroll
        for (int h = 0; h < 4; ++h) {
            atomicAdd(&g_R[gj * 4 + h], sAcc[SRJ + cl * 4 + h]);
            float cn = sAcc[SCNJ + cl * 4 + h];
            if (cn != 0.f) atomicAdd(&g_cnt[gj * 4 + h], cn);
        }
    }
}

// ---------------- finalize ----------------
// sum_mask log_prob = ln2 * ( sum d_biased - sum_h cnt_h * lg2(R_raw_h) )  (64*ct cancels)
__global__ void finalK(float* __restrict__ out) {
    __shared__ float ss[512], sc[512];
    int tid = threadIdx.x;
    float s = 0.f, c = 0.f;
    for (int i = tid; i < N_; i += 512) {
        float ct = 0.f;
        float acc = g_dot[i];
#pragma unroll
        for (int h = 0; h < 4; ++h) {
            float cn = g_cnt[i * 4 + h];
            ct  += cn;
            acc -= cn * lg2f(g_R[i * 4 + h]);
        }
        float loss = -0.6931471805599453f * acc / ct;   // NaN when ct==0, as in reference
        if (isfinite(loss)) { s += loss; c += 1.f; }
    }
    ss[tid] = s; sc[tid] = c;
    __syncthreads();
    for (int o = 256; o; o >>= 1) {
        if (tid < o) { ss[tid] += ss[tid + o]; sc[tid] += sc[tid + o]; }
        __syncthreads();
    }
    if (tid == 0) out[0] = ss[0] / sc[0];
}

// ---------------- launch ----------------
extern "C" void kernel_launch(void* const* d_in, const int* in_sizes, int n_in,
                              void* d_out, int out_size) {
    const float* features = (const float*)d_in[0];
    const float* labels   = (const float*)d_in[1];
    float* out = (float*)d_out;

    cudaFuncSetAttribute(mainK, cudaFuncAttributeMaxDynamicSharedMemorySize, SMEM_TOTAL);

    preK<<<N_ / 4, 256>>>(features, labels);
    mainK<<<NCTA, THREADS, SMEM_TOTAL>>>();
    finalK<<<1, 512>>>(out);
}